// round 15
// baseline (speedup 1.0000x reference)
#include <cuda_runtime.h>
#include <cuda_bf16.h>
#include <math.h>
#include <stdint.h>

// ---------------------------------------------------------------------------
// CfC / AutoNCP decoder — wavefront-pipelined, mma.sync bf16 hi/lo split,
// SPLIT-K x2: two blocks per output tile (kh = bx&1), partial sums reduced
// by the last-arriving block (threadfence + atomicInc), which then runs the
// fused CfC epilogue. Doubles resident warps to hide the per-warp serial core.
//   layer l at wavefront s computes t = s - l
//   GEMMs: D = Ahi*Bhi + Ahi*Blo + Alo*Bhi  (lo*lo dropped, ~2^-16 rel)
// ---------------------------------------------------------------------------

#define BB   512
#define TT   128
#define IDIM 512
#define OUTD 128

#define N0 538
#define N1 358
#define N2 128

// padded h widths (multiples of 8) and reordered K' = n4 + in_dim
#define NP0 544
#define NP1 360
#define NP2P 128
#define NT0 33
#define NT1 29
#define NT2 16
// split-K boundaries
#define NTH0 17
#define NTH1 15
#define NTH2 8
#define KW0 (NT0*32)   // 1056 words/row in packed weight layout
#define KW1 (NT1*32)   // 928
#define KW2 (NT2*32)   // 512

#define QS0 (N0*KW0)
#define QS1 (N1*KW1)
#define QS2 (N2*KW2)
#define QOFF1 (QS0)
#define QOFF2 (QS0+QS1)
#define QTOT  (QS0+QS1+QS2)

#define OFFH0 0
#define OFFH1 (BB*NP0)
#define OFFH2 (BB*(NP0+NP1))
#define HTOTP (BB*(NP0+NP1+NP2P) + 1024)

// tile partition (BM=64, BN=16)
#define TIL_L0 272    // 34 col-tiles x 8 row-tiles
#define TIL_L1 184    // 23 x 8
#define TIL_L2 64     //  8 x 8
#define TIL_TOT (TIL_L0 + TIL_L1 + TIL_L2)   // 520
#define BLK_TOT (2 * TIL_TOT)                // 1040 (x2 split-K)

// Static device scratch (no runtime allocation).
__device__ __align__(16) uint32_t gWq1[QTOT];
__device__ __align__(16) uint32_t gWq2[QTOT];
__device__ __align__(16) uint32_t gWqab[QTOT];
__device__ __align__(16) float gH[2][HTOTP];   // parity double buffer, padded rows
// split-K partials: [kh][tile][tid][24 floats]
__device__ __align__(16) float gPart[2 * TIL_TOT * 128 * 24];
__device__ unsigned gCnt[TIL_TOT];             // zero-init; atomicInc(.,1) auto-wraps

// ---------------------------------------------------------------------------
// helpers
// ---------------------------------------------------------------------------
__device__ __forceinline__ int remap_k(int kp, int n, int n4, int in_dim)
{
    if (kp < n4) return (kp < n) ? (in_dim + kp) : -1;
    int ks = kp - n4;
    return (ks < in_dim) ? ks : -1;
}

__device__ __forceinline__ uint32_t pack_sel(float f0, float f1, int isLo)
{
    __nv_bfloat16 h0 = __float2bfloat16_rn(f0);
    __nv_bfloat16 h1 = __float2bfloat16_rn(f1);
    if (isLo) {
        h0 = __float2bfloat16_rn(f0 - __bfloat162float(h0));
        h1 = __float2bfloat16_rn(f1 - __bfloat162float(h1));
    }
    return ((uint32_t)__bfloat16_as_ushort(h1) << 16) | (uint32_t)__bfloat16_as_ushort(h0);
}

__device__ __forceinline__ void split2(float f0, float f1, uint32_t& hi, uint32_t& lo)
{
    __nv_bfloat16 h0 = __float2bfloat16_rn(f0);
    __nv_bfloat16 h1 = __float2bfloat16_rn(f1);
    float r0 = f0 - __bfloat162float(h0);
    float r1 = f1 - __bfloat162float(h1);
    __nv_bfloat16 l0 = __float2bfloat16_rn(r0);
    __nv_bfloat16 l1 = __float2bfloat16_rn(r1);
    hi = ((uint32_t)__bfloat16_as_ushort(h1) << 16) | (uint32_t)__bfloat16_as_ushort(h0);
    lo = ((uint32_t)__bfloat16_as_ushort(l1) << 16) | (uint32_t)__bfloat16_as_ushort(l0);
}

__device__ __forceinline__ void mma16816(float* c, const uint32_t* a, uint32_t b0, uint32_t b1)
{
    asm volatile(
        "mma.sync.aligned.m16n8k16.row.col.f32.bf16.bf16.f32 "
        "{%0,%1,%2,%3}, {%4,%5,%6,%7}, {%8,%9}, {%0,%1,%2,%3};\n"
        : "+f"(c[0]), "+f"(c[1]), "+f"(c[2]), "+f"(c[3])
        : "r"(a[0]), "r"(a[1]), "r"(a[2]), "r"(a[3]), "r"(b0), "r"(b1));
}

__device__ __forceinline__ void cp16u(void* dst, const void* src)
{
    uint32_t d = (uint32_t)__cvta_generic_to_shared(dst);
    asm volatile("cp.async.cg.shared.global [%0], [%1], 16;\n" :: "r"(d), "l"(src) : "memory");
}
__device__ __forceinline__ void cp16p(void* dst, const void* src, bool pred)
{
    uint32_t d = (uint32_t)__cvta_generic_to_shared(dst);
    const void* s = pred ? src : (const void*)gWq1;   // 16B-aligned safe address
    int sz = pred ? 16 : 0;                            // 0 -> zero-fill 16B
    asm volatile("cp.async.cg.shared.global [%0], [%1], 16, %2;\n"
                 :: "r"(d), "l"(s), "r"(sz) : "memory");
}
__device__ __forceinline__ void cp_commit() { asm volatile("cp.async.commit_group;\n" ::: "memory"); }
template <int N>
__device__ __forceinline__ void cp_wait() { asm volatile("cp.async.wait_group %0;\n" :: "n"(N) : "memory"); }

// ---------------------------------------------------------------------------
// prep: build packed bf16 hi/lo weights (masked / summed, reordered, padded)
// ---------------------------------------------------------------------------
__global__ void prep_kernel(
    const float* __restrict__ W1_0, const float* __restrict__ W2_0,
    const float* __restrict__ Wa_0, const float* __restrict__ Wb_0, const float* __restrict__ m0,
    const float* __restrict__ W1_1, const float* __restrict__ W2_1,
    const float* __restrict__ Wa_1, const float* __restrict__ Wb_1, const float* __restrict__ m1,
    const float* __restrict__ W1_2, const float* __restrict__ W2_2,
    const float* __restrict__ Wa_2, const float* __restrict__ Wb_2, const float* __restrict__ m2)
{
    for (int i = blockIdx.x * blockDim.x + threadIdx.x; i < QTOT; i += gridDim.x * blockDim.x) {
        const float *W1, *W2, *Wa, *Wb, *m;
        int li, n, n4, in_dim, K, KW;
        if (i < QOFF1) {
            W1=W1_0; W2=W2_0; Wa=Wa_0; Wb=Wb_0; m=m0;
            li=i; n=N0; n4=NP0; in_dim=IDIM; KW=KW0;
        } else if (i < QOFF2) {
            W1=W1_1; W2=W2_1; Wa=Wa_1; Wb=Wb_1; m=m1;
            li=i-QOFF1; n=N1; n4=NP1; in_dim=N0; KW=KW1;
        } else {
            W1=W1_2; W2=W2_2; Wa=Wa_2; Wb=Wb_2; m=m2;
            li=i-QOFF2; n=N2; n4=NP2P; in_dim=N1; KW=KW2;
        }
        K = in_dim + n;
        int j = li / KW;
        int w = li - j * KW;
        int p = w >> 1, isLo = w & 1;
        int s0 = remap_k(2*p,     n, n4, in_dim);
        int s1 = remap_k(2*p + 1, n, n4, in_dim);

        float a0=0.f, a1=0.f, b0v=0.f, b1v=0.f, c0=0.f, c1=0.f;
        if (s0 >= 0) {
            int ix = j*K + s0; float mm = m[ix];
            a0 = W1[ix]*mm; b0v = W2[ix]*mm; c0 = Wa[ix] + Wb[ix];
        }
        if (s1 >= 0) {
            int ix = j*K + s1; float mm = m[ix];
            a1 = W1[ix]*mm; b1v = W2[ix]*mm; c1 = Wa[ix] + Wb[ix];
        }
        gWq1[i]  = pack_sel(a0,  a1,  isLo);
        gWq2[i]  = pack_sel(b0v, b1v, isLo);
        gWqab[i] = pack_sel(c0,  c1,  isLo);
    }
}

// h0 -> per-layer padded-row state, both parities (pad cols stay zero-init)
__global__ void init_h_kernel(const float* __restrict__ h0)
{
    for (int idx = blockIdx.x * blockDim.x + threadIdx.x; idx < BB*1024; idx += gridDim.x * blockDim.x) {
        int b = idx >> 10;
        int c = idx & 1023;
        float v = h0[idx];
        int off;
        if (c < N0)           off = OFFH0 + b * NP0 + c;
        else if (c < N0 + N1) off = OFFH1 + b * NP1 + (c - N0);
        else                  off = OFFH2 + b * NP2P + (c - N0 - N1);
        gH[0][off] = v;
        gH[1][off] = v;
    }
}

// final h: layer0 parity 1 (s=127), layer1 parity 0 (s=128), layer2 parity 1 (s=129)
__global__ void copy_hn_kernel(float* __restrict__ hn)
{
    for (int idx = blockIdx.x * blockDim.x + threadIdx.x; idx < BB*1024; idx += gridDim.x * blockDim.x) {
        int b = idx >> 10;
        int c = idx & 1023;
        float v;
        if (c < N0)           v = gH[1][OFFH0 + b * NP0 + c];
        else if (c < N0 + N1) v = gH[0][OFFH1 + b * NP1 + (c - N0)];
        else                  v = gH[1][OFFH2 + b * NP2P + (c - N0 - N1)];
        hn[idx] = v;
    }
}

// smem strides (words). Same as the measured-best R9/R14 kernel.
#define AP 40   // As[row][k] fp32, 40 floats/row (160B)
#define WP 40   // Bs[mat][col][word], 40 words/col (160B)

// ---------------------------------------------------------------------------
// Fused CfC cell, split-K half. 128 threads = 4 warps.
//   BM=64 (warp w owns rows w*16..w*16+15), BN=16 (2 n8 tiles), BK=32.
//   kh selects k-tile range; last-arriving block reduces + runs epilogue.
// ---------------------------------------------------------------------------
template <int L>
__device__ __forceinline__ void cell_mma(
    int bidx, int t, int wp, int kh, int tileG,
    const float* __restrict__ x,
    const float* __restrict__ b1, const float* __restrict__ b2,
    const float* __restrict__ ba, const float* __restrict__ bb,
    float* __restrict__ out,
    float (*As)[64][AP], uint32_t (*Bs)[3][16][WP])
{
    constexpr int n    = (L==0) ? N0 : (L==1) ? N1 : N2;
    constexpr int n4   = (L==0) ? NP0 : (L==1) ? NP1 : NP2P;
    constexpr int NT   = (L==0) ? NT0 : (L==1) ? NT1 : NT2;
    constexpr int NTH  = (L==0) ? NTH0 : (L==1) ? NTH1 : NTH2;
    constexpr int KW   = NT * 32;
    constexpr int COLT = (L==0) ? 34 : (L==1) ? 23 : 8;
    constexpr int NPl  = n4;
    constexpr int NPin = (L==1) ? NP0 : (L==2) ? NP1 : 0;
    constexpr int hoff = (L==0) ? OFFH0 : (L==1) ? OFFH1 : OFFH2;
    constexpr int qoff = (L==0) ? 0 : (L==1) ? QOFF1 : QOFF2;
    constexpr int ioff = (L==1) ? OFFH0 : (L==2) ? OFFH1 : 0;

    const float* prev = gH[wp ^ 1];
    const float* inA  = (L==0) ? (x + (size_t)t * IDIM) : (prev + ioff);
    const int    ldA  = (L==0) ? (TT * IDIM) : NPin;
    const float* hcur = prev + hoff;
    float*       hout = gH[wp] + hoff;

    const int tid  = threadIdx.x;
    const int lane = tid & 31;
    const int warp = tid >> 5;
    const int g    = lane >> 2;
    const int tig  = lane & 3;
    const int rowBase = (bidx / COLT) * 64;
    const int colBase = (bidx % COLT) * 16;

    const int i0 = kh ? NTH : 0;
    const int i1 = kh ? NT  : NTH;

    float acc[2][3][4];
#pragma unroll
    for (int nt = 0; nt < 2; nt++)
#pragma unroll
        for (int m = 0; m < 3; m++)
#pragma unroll
            for (int q = 0; q < 4; q++) acc[nt][m][q] = 0.f;

    // ---- cp.async tile issue (A: 512 16B-chunks, W: 384) ----
    auto issue = [&](int kt, int st) {
#pragma unroll
        for (int i = 0; i < 4; i++) {
            int idx = tid + i * 128;
            int r = idx >> 3, ch = idx & 7;
            int g0 = kt * 32 + ch * 4;
            const float* src = (g0 < n4)
                ? (hcur + (size_t)(rowBase + r) * NPl + g0)
                : (inA + (size_t)(rowBase + r) * ldA + (g0 - n4));
            cp16u(&As[st][r][ch * 4], src);
        }
#pragma unroll
        for (int i = 0; i < 3; i++) {
            int idx = tid + i * 128;
            int mat = idx >> 7;
            int r = idx & 127;
            int c = r >> 3, ch = r & 7;
            int jn = colBase + c;
            const uint32_t* src =
                ((mat == 0) ? gWq1 : (mat == 1) ? gWq2 : gWqab)
                + qoff + (size_t)(jn < n ? jn : 0) * KW + kt * 32 + ch * 4;
            cp16p(&Bs[st][mat][c][ch * 4], src, jn < n);
        }
    };

    issue(i0, 0);
    cp_commit();

    for (int kt = i0; kt < i1; kt++) {
        const int st = (kt - i0) & 1;
        if (kt + 1 < i1) {
            issue(kt + 1, st ^ 1);
            cp_commit();
            cp_wait<1>();
        } else {
            cp_wait<0>();
        }
        __syncthreads();

        // hoist fragments for this k-tile
        const int r0 = warp * 16 + g;
        uint32_t ahi[2][4], alo[2][4];
#pragma unroll
        for (int c16 = 0; c16 < 2; c16++) {
            const int kc = c16 * 16 + 2 * tig;
            float2 v0 = *(const float2*)&As[st][r0][kc];
            float2 v1 = *(const float2*)&As[st][r0 + 8][kc];
            float2 v2 = *(const float2*)&As[st][r0][kc + 8];
            float2 v3 = *(const float2*)&As[st][r0 + 8][kc + 8];
            split2(v0.x, v0.y, ahi[c16][0], alo[c16][0]);
            split2(v1.x, v1.y, ahi[c16][1], alo[c16][1]);
            split2(v2.x, v2.y, ahi[c16][2], alo[c16][2]);
            split2(v3.x, v3.y, ahi[c16][3], alo[c16][3]);
        }
#pragma unroll
        for (int nt = 0; nt < 2; nt++) {
#pragma unroll
            for (int m = 0; m < 3; m++) {
#pragma unroll
                for (int c16 = 0; c16 < 2; c16++) {
                    uint2 w0 = *(const uint2*)&Bs[st][m][nt * 8 + g][2 * (c16 * 8 + tig)];
                    uint2 w1 = *(const uint2*)&Bs[st][m][nt * 8 + g][2 * (c16 * 8 + tig + 4)];
                    mma16816(acc[nt][m], ahi[c16], w0.x, w1.x);
                    mma16816(acc[nt][m], ahi[c16], w0.y, w1.y);
                    mma16816(acc[nt][m], alo[c16], w0.x, w1.x);
                }
            }
        }
        __syncthreads();
    }

    // ---- split-K reduction: write partials, last block reduces ----
    float* part = gPart + (((size_t)kh * TIL_TOT + tileG) * 128 + tid) * 24;
#pragma unroll
    for (int nt = 0; nt < 2; nt++)
#pragma unroll
        for (int m = 0; m < 3; m++)
            *(float4*)(part + (nt * 3 + m) * 4) =
                make_float4(acc[nt][m][0], acc[nt][m][1], acc[nt][m][2], acc[nt][m][3]);
    __threadfence();
    __syncthreads();
    __shared__ unsigned sOld;
    if (tid == 0) sOld = atomicInc(&gCnt[tileG], 1);   // auto-wraps 1 -> 0
    __syncthreads();
    if (sOld == 0) return;          // first arriver exits; partner will reduce
    __threadfence();                // acquire partner's partials

    const float* pp = gPart + (((size_t)(kh ^ 1) * TIL_TOT + tileG) * 128 + tid) * 24;
#pragma unroll
    for (int nt = 0; nt < 2; nt++)
#pragma unroll
        for (int m = 0; m < 3; m++) {
            float4 v = *(const float4*)(pp + (nt * 3 + m) * 4);
            acc[nt][m][0] += v.x; acc[nt][m][1] += v.y;
            acc[nt][m][2] += v.z; acc[nt][m][3] += v.w;
        }

    // ---- fused CfC epilogue (C frag: rows g,g+8 ; cols 2tig,2tig+1) ----
    const int r0g = rowBase + warp * 16 + g;
#pragma unroll
    for (int nt = 0; nt < 2; nt++) {
#pragma unroll
        for (int cp = 0; cp < 2; cp++) {
            const int j = colBase + nt * 8 + 2 * tig + cp;
            if (j < n) {
                const float vb1 = b1[j], vb2 = b2[j], vbs = ba[j] + bb[j];
#pragma unroll
                for (int half = 0; half < 2; half++) {
                    const int gr = r0g + half * 8;
                    const float s1 = acc[nt][0][half * 2 + cp];
                    const float s2 = acc[nt][1][half * 2 + cp];
                    const float s3 = acc[nt][2][half * 2 + cp];
                    const float f1 = tanhf(s1 + vb1);
                    const float f2 = tanhf(s2 + vb2);
                    const float ti = 1.f / (1.f + expf(-(s3 + vbs)));
                    const float hv = f1 + ti * (f2 - f1);
                    hout[(size_t)gr * NPl + j] = hv;
                    if (L == 2) out[(size_t)gr * (TT * OUTD) + (size_t)t * OUTD + j] = hv;
                }
            }
        }
    }
}

// ---------------------------------------------------------------------------
// One wavefront: layer l active when 0 <= s-l < 128.
// Grid = 1040 blocks; tile = bx>>1, kh = bx&1 (partners adjacent).
// ---------------------------------------------------------------------------
__global__ __launch_bounds__(128, 5) void wave_kernel(
    int s, const float* __restrict__ x,
    const float* __restrict__ b1_0, const float* __restrict__ b2_0,
    const float* __restrict__ ba_0, const float* __restrict__ bb_0,
    const float* __restrict__ b1_1, const float* __restrict__ b2_1,
    const float* __restrict__ ba_1, const float* __restrict__ bb_1,
    const float* __restrict__ b1_2, const float* __restrict__ b2_2,
    const float* __restrict__ ba_2, const float* __restrict__ bb_2,
    float* __restrict__ out)
{
    __shared__ float    As[2][64][AP];
    __shared__ uint32_t Bs[2][3][16][WP];

    const int bx   = blockIdx.x;
    const int tile = bx >> 1;
    const int kh   = bx & 1;
    const int wp   = s & 1;

    if (tile < TIL_L0) {
        if (s < TT)
            cell_mma<0>(tile, s, wp, kh, tile, x, b1_0, b2_0, ba_0, bb_0, nullptr, As, Bs);
    } else if (tile < TIL_L0 + TIL_L1) {
        int t = s - 1;
        if (t >= 0 && t < TT)
            cell_mma<1>(tile - TIL_L0, t, wp, kh, tile, x, b1_1, b2_1, ba_1, bb_1, nullptr, As, Bs);
    } else {
        int t = s - 2;
        if (t >= 0 && t < TT)
            cell_mma<2>(tile - TIL_L0 - TIL_L1, t, wp, kh, tile, x, b1_2, b2_2, ba_2, bb_2, out, As, Bs);
    }
}

// ---------------------------------------------------------------------------
// Final FC, in-place on d_out predictions region.
// ---------------------------------------------------------------------------
__global__ __launch_bounds__(256) void fc_kernel(float* __restrict__ pred,
                                                 const float* __restrict__ Wfc,
                                                 const float* __restrict__ bfc)
{
    __shared__ float As[64][129];
    const int tid  = threadIdx.x;
    const int lane = tid & 31;
    const int wrp  = tid >> 5;
    float* base = pred + (size_t)blockIdx.x * 64 * OUTD;

    for (int e = tid; e < 64 * OUTD; e += 256)
        As[e >> 7][e & 127] = base[e];
    __syncthreads();

    for (int jj = 0; jj < 16; jj++) {
        int j = jj * 8 + wrp;
        float acc0 = bfc[j], acc1 = bfc[j];
        const float* wr = Wfc + j * OUTD;
#pragma unroll 8
        for (int k = 0; k < OUTD; k++) {
            float wv = wr[k];
            acc0 += As[lane][k] * wv;
            acc1 += As[lane + 32][k] * wv;
        }
        base[lane * OUTD + j]        = acc0;
        base[(lane + 32) * OUTD + j] = acc1;
    }
}

// ---------------------------------------------------------------------------
extern "C" void kernel_launch(void* const* d_in, const int* in_sizes, int n_in,
                              void* d_out, int out_size)
{
    const float* x    = (const float*)d_in[0];
    const float* h0   = (const float*)d_in[1];

    const float* mask0 = (const float*)d_in[2];
    const float* W1_0  = (const float*)d_in[3];
    const float* W2_0  = (const float*)d_in[4];
    const float* Wa_0  = (const float*)d_in[5];
    const float* Wb_0  = (const float*)d_in[6];
    const float* b1_0  = (const float*)d_in[7];
    const float* b2_0  = (const float*)d_in[8];
    const float* ba_0  = (const float*)d_in[9];
    const float* bb_0  = (const float*)d_in[10];

    const float* mask1 = (const float*)d_in[11];
    const float* W1_1  = (const float*)d_in[12];
    const float* W2_1  = (const float*)d_in[13];
    const float* Wa_1  = (const float*)d_in[14];
    const float* Wb_1  = (const float*)d_in[15];
    const float* b1_1  = (const float*)d_in[16];
    const float* b2_1  = (const float*)d_in[17];
    const float* ba_1  = (const float*)d_in[18];
    const float* bb_1  = (const float*)d_in[19];

    const float* mask2 = (const float*)d_in[20];
    const float* W1_2  = (const float*)d_in[21];
    const float* W2_2  = (const float*)d_in[22];
    const float* Wa_2  = (const float*)d_in[23];
    const float* Wb_2  = (const float*)d_in[24];
    const float* b1_2  = (const float*)d_in[25];
    const float* b2_2  = (const float*)d_in[26];
    const float* ba_2  = (const float*)d_in[27];
    const float* bb_2  = (const float*)d_in[28];

    const float* Wfc  = (const float*)d_in[29];
    const float* bfc  = (const float*)d_in[30];

    float* out = (float*)d_out;

    prep_kernel<<<2048, 256>>>(W1_0, W2_0, Wa_0, Wb_0, mask0,
                               W1_1, W2_1, Wa_1, Wb_1, mask1,
                               W1_2, W2_2, Wa_2, Wb_2, mask2);
    init_h_kernel<<<1024, 256>>>(h0);

    // Wavefront sweep: s = 0 .. 129 (layer l computes t = s - l)
    for (int s = 0; s < TT + 2; s++) {
        wave_kernel<<<BLK_TOT, 128>>>(s, x,
                                      b1_0, b2_0, ba_0, bb_0,
                                      b1_1, b2_1, ba_1, bb_1,
                                      b1_2, b2_2, ba_2, bb_2,
                                      out);
    }

    // predictions = motor @ Wfc^T + bfc (in place)
    fc_kernel<<<(BB * TT) / 64, 256>>>(out, Wfc, bfc);

    if (out_size >= BB * TT * OUTD + BB * 1024)
        copy_hn_kernel<<<1024, 256>>>(out + (size_t)BB * TT * OUTD);
}

// round 16
// speedup vs baseline: 1.0786x; 1.0786x over previous
#include <cuda_runtime.h>
#include <cuda_bf16.h>
#include <math.h>
#include <stdint.h>

// ---------------------------------------------------------------------------
// CfC / AutoNCP decoder — wavefront-pipelined, mma.sync bf16 hi/lo split.
// Packed-A variant with conflict-free smem strides (AP=WP=40 words):
// hidden state and pre-split x stored as interleaved bf16 hi/lo words
// (same format as weights), so the mainloop has ZERO conversion work:
//   word 2p   = bf16x2{ hi(elem 2p), hi(elem 2p+1) }
//   word 2p+1 = bf16x2{ lo(elem 2p), lo(elem 2p+1) }
// GEMMs: D = Ahi*Bhi + Ahi*Blo + Alo*Bhi  (lo*lo dropped, ~2^-16 rel)
//   layer l at wavefront s computes t = s - l
// ---------------------------------------------------------------------------

#define BB   512
#define TT   128
#define IDIM 512
#define OUTD 128

#define N0 538
#define N1 358
#define N2 128

// padded h widths (row strides in words == elements)
#define NP0 544
#define NP1 360
#define NP2P 128
// input-region padded widths
#define NPIN0 512
#define NPIN1 NP0
#define NPIN2 NP1
// total A-row words per layer and k-tiles of 32
#define AW0 (NP0 + NPIN0)   // 1056
#define AW1 (NP1 + NPIN1)   // 904
#define AW2 (NP2P + NPIN2)  // 488
#define NT0 33
#define NT1 29
#define NT2 16
#define KW0 (NT0*32)
#define KW1 (NT1*32)
#define KW2 (NT2*32)

#define QS0 (N0*KW0)
#define QS1 (N1*KW1)
#define QS2 (N2*KW2)
#define QOFF1 (QS0)
#define QOFF2 (QS0+QS1)
#define QTOT  (QS0+QS1+QS2)

// packed hidden-state offsets (words)
#define OFFQ0 0
#define OFFQ1 (BB*NP0)
#define OFFQ2 (BB*(NP0+NP1))
#define HTOTQ (BB*(NP0+NP1+NP2P))

// wavefront grid partition (BM=64, BN=16)
#define BLK_L0 272    // 34 col-tiles x 8 row-tiles
#define BLK_L1 184    // 23 x 8
#define BLK_L2 64     //  8 x 8
#define BLK_TOT (BLK_L0 + BLK_L1 + BLK_L2)   // 520

// Static device scratch (zero-initialized at module load; pads never written)
__device__ __align__(16) uint32_t gWq1[QTOT];
__device__ __align__(16) uint32_t gWq2[QTOT];
__device__ __align__(16) uint32_t gWqab[QTOT];
__device__ __align__(16) uint32_t gHq[2][HTOTQ];
__device__ __align__(16) uint32_t gXq[BB * TT * IDIM];

// ---------------------------------------------------------------------------
// helpers
// ---------------------------------------------------------------------------
__device__ __forceinline__ void split2(float f0, float f1, uint32_t& hi, uint32_t& lo)
{
    __nv_bfloat16 h0 = __float2bfloat16_rn(f0);
    __nv_bfloat16 h1 = __float2bfloat16_rn(f1);
    float r0 = f0 - __bfloat162float(h0);
    float r1 = f1 - __bfloat162float(h1);
    __nv_bfloat16 l0 = __float2bfloat16_rn(r0);
    __nv_bfloat16 l1 = __float2bfloat16_rn(r1);
    hi = ((uint32_t)__bfloat16_as_ushort(h1) << 16) | (uint32_t)__bfloat16_as_ushort(h0);
    lo = ((uint32_t)__bfloat16_as_ushort(l1) << 16) | (uint32_t)__bfloat16_as_ushort(l0);
}
__device__ __forceinline__ float bf_lo(uint32_t w)
{
    return __bfloat162float(__ushort_as_bfloat16((unsigned short)(w & 0xffff)));
}
__device__ __forceinline__ float bf_hi(uint32_t w)
{
    return __bfloat162float(__ushort_as_bfloat16((unsigned short)(w >> 16)));
}

__device__ __forceinline__ void mma16816(float* c, const uint32_t* a, uint32_t b0, uint32_t b1)
{
    asm volatile(
        "mma.sync.aligned.m16n8k16.row.col.f32.bf16.bf16.f32 "
        "{%0,%1,%2,%3}, {%4,%5,%6,%7}, {%8,%9}, {%0,%1,%2,%3};\n"
        : "+f"(c[0]), "+f"(c[1]), "+f"(c[2]), "+f"(c[3])
        : "r"(a[0]), "r"(a[1]), "r"(a[2]), "r"(a[3]), "r"(b0), "r"(b1));
}

__device__ __forceinline__ void cp16p(void* dst, const void* src, bool pred)
{
    uint32_t d = (uint32_t)__cvta_generic_to_shared(dst);
    const void* s = pred ? src : (const void*)gWq1;   // 16B-aligned safe address
    int sz = pred ? 16 : 0;                            // 0 -> zero-fill 16B
    asm volatile("cp.async.cg.shared.global [%0], [%1], 16, %2;\n"
                 :: "r"(d), "l"(s), "r"(sz) : "memory");
}
__device__ __forceinline__ void cp_commit() { asm volatile("cp.async.commit_group;\n" ::: "memory"); }
template <int N>
__device__ __forceinline__ void cp_wait() { asm volatile("cp.async.wait_group %0;\n" :: "n"(N) : "memory"); }

// ---------------------------------------------------------------------------
// prep: packed bf16 hi/lo weights. k' order = [own h (n4), input (NPin)]
// ---------------------------------------------------------------------------
__device__ __forceinline__ int remap_k(int kp, int n, int n4, int in_real)
{
    if (kp < n4) return (kp < n) ? (in_real + kp) : -1;
    int ks = kp - n4;
    return (ks < in_real) ? ks : -1;
}
__device__ __forceinline__ uint32_t pack_sel(float f0, float f1, int isLo)
{
    uint32_t hi, lo;
    split2(f0, f1, hi, lo);
    return isLo ? lo : hi;
}

__global__ void prep_kernel(
    const float* __restrict__ W1_0, const float* __restrict__ W2_0,
    const float* __restrict__ Wa_0, const float* __restrict__ Wb_0, const float* __restrict__ m0,
    const float* __restrict__ W1_1, const float* __restrict__ W2_1,
    const float* __restrict__ Wa_1, const float* __restrict__ Wb_1, const float* __restrict__ m1,
    const float* __restrict__ W1_2, const float* __restrict__ W2_2,
    const float* __restrict__ Wa_2, const float* __restrict__ Wb_2, const float* __restrict__ m2)
{
    for (int i = blockIdx.x * blockDim.x + threadIdx.x; i < QTOT; i += gridDim.x * blockDim.x) {
        const float *W1, *W2, *Wa, *Wb, *m;
        int li, n, n4, in_real, K, KW;
        if (i < QOFF1) {
            W1=W1_0; W2=W2_0; Wa=Wa_0; Wb=Wb_0; m=m0;
            li=i; n=N0; n4=NP0; in_real=IDIM; KW=KW0;
        } else if (i < QOFF2) {
            W1=W1_1; W2=W2_1; Wa=Wa_1; Wb=Wb_1; m=m1;
            li=i-QOFF1; n=N1; n4=NP1; in_real=N0; KW=KW1;
        } else {
            W1=W1_2; W2=W2_2; Wa=Wa_2; Wb=Wb_2; m=m2;
            li=i-QOFF2; n=N2; n4=NP2P; in_real=N1; KW=KW2;
        }
        K = in_real + n;
        int j = li / KW;
        int w = li - j * KW;
        int p = w >> 1, isLo = w & 1;
        int s0 = remap_k(2*p,     n, n4, in_real);
        int s1 = remap_k(2*p + 1, n, n4, in_real);

        float a0=0.f, a1=0.f, b0v=0.f, b1v=0.f, c0=0.f, c1=0.f;
        if (s0 >= 0) {
            int ix = j*K + s0; float mm = m[ix];
            a0 = W1[ix]*mm; b0v = W2[ix]*mm; c0 = Wa[ix] + Wb[ix];
        }
        if (s1 >= 0) {
            int ix = j*K + s1; float mm = m[ix];
            a1 = W1[ix]*mm; b1v = W2[ix]*mm; c1 = Wa[ix] + Wb[ix];
        }
        gWq1[i]  = pack_sel(a0,  a1,  isLo);
        gWq2[i]  = pack_sel(b0v, b1v, isLo);
        gWqab[i] = pack_sel(c0,  c1,  isLo);
    }
}

// pre-split x into packed hi/lo words (layout mirrors x element order)
__global__ void prep_x_kernel(const float* __restrict__ x)
{
    const int total = BB * TT * IDIM / 2;
    for (int p = blockIdx.x * blockDim.x + threadIdx.x; p < total; p += gridDim.x * blockDim.x) {
        float2 v = *(const float2*)(x + 2 * (size_t)p);
        uint32_t hi, lo;
        split2(v.x, v.y, hi, lo);
        gXq[2 * (size_t)p]     = hi;
        gXq[2 * (size_t)p + 1] = lo;
    }
}

// h0 -> packed per-layer state, both parities
__global__ void init_h_kernel(const float* __restrict__ h0)
{
    const int total = BB * 512;
    for (int idx = blockIdx.x * blockDim.x + threadIdx.x; idx < total; idx += gridDim.x * blockDim.x) {
        int b = idx >> 9;
        int p = idx & 511;
        int c0 = 2 * p;
        int off, lc0;
        if (c0 < N0)           { off = OFFQ0 + b * NP0;  lc0 = c0; }
        else if (c0 < N0 + N1) { off = OFFQ1 + b * NP1;  lc0 = c0 - N0; }
        else                   { off = OFFQ2 + b * NP2P; lc0 = c0 - N0 - N1; }
        uint32_t hi, lo;
        split2(h0[b * 1024 + c0], h0[b * 1024 + c0 + 1], hi, lo);
        gHq[0][off + lc0]     = hi;
        gHq[0][off + lc0 + 1] = lo;
        gHq[1][off + lc0]     = hi;
        gHq[1][off + lc0 + 1] = lo;
    }
}

// final h: layer0 parity 1 (s=127), layer1 parity 0 (s=128), layer2 parity 1 (s=129)
__global__ void copy_hn_kernel(float* __restrict__ hn)
{
    const int total = BB * 512;
    for (int idx = blockIdx.x * blockDim.x + threadIdx.x; idx < total; idx += gridDim.x * blockDim.x) {
        int b = idx >> 9;
        int p = idx & 511;
        int c0 = 2 * p;
        const uint32_t* src;
        int lc0;
        if (c0 < N0)           { src = gHq[1] + OFFQ0 + b * NP0;  lc0 = c0; }
        else if (c0 < N0 + N1) { src = gHq[0] + OFFQ1 + b * NP1;  lc0 = c0 - N0; }
        else                   { src = gHq[1] + OFFQ2 + b * NP2P; lc0 = c0 - N0 - N1; }
        uint32_t hi = src[lc0], lo = src[lc0 + 1];
        hn[b * 1024 + c0]     = bf_lo(hi) + bf_lo(lo);
        hn[b * 1024 + c0 + 1] = bf_hi(hi) + bf_hi(lo);
    }
}

// smem strides (words): stride 40 -> bank = (8g + 2tig) mod 32, conflict-free
// LDS.64 per half-warp phase for BOTH A and B fragment loads (the R10 retry
// failed on AAP=36, whose 4g+2tig pattern collides 2-way).
#define AAP 40   // As[row][word]
#define WP  40   // Bs[mat][col][word]

// ---------------------------------------------------------------------------
// Fused CfC cell, mma.sync, packed-A, zero in-loop conversions.
//   128 threads = 4 warps. BM=64 (warp w: rows w*16..w*16+15), BN=16, BK=32.
//   All fragments hoisted per k-tile, then a 36-HMMA burst on 6 acc chains.
// ---------------------------------------------------------------------------
template <int L>
__device__ __forceinline__ void cell_mma(
    int bidx, int t, int wp,
    const float* __restrict__ b1, const float* __restrict__ b2,
    const float* __restrict__ ba, const float* __restrict__ bb,
    float* __restrict__ out,
    uint32_t (*As)[64][AAP], uint32_t (*Bs)[3][16][WP])
{
    constexpr int n    = (L==0) ? N0 : (L==1) ? N1 : N2;
    constexpr int n4   = (L==0) ? NP0 : (L==1) ? NP1 : NP2P;
    constexpr int NPin = (L==0) ? NPIN0 : (L==1) ? NPIN1 : NPIN2;
    constexpr int AW   = n4 + NPin;
    constexpr int NT   = (L==0) ? NT0 : (L==1) ? NT1 : NT2;
    constexpr int KW   = NT * 32;
    constexpr int COLT = (L==0) ? 34 : (L==1) ? 23 : 8;
    constexpr int hoffq = (L==0) ? OFFQ0 : (L==1) ? OFFQ1 : OFFQ2;
    constexpr int qoff  = (L==0) ? 0 : (L==1) ? QOFF1 : QOFF2;
    constexpr int ioffq = (L==1) ? OFFQ0 : (L==2) ? OFFQ1 : 0;

    const uint32_t* prev = gHq[wp ^ 1];
    const uint32_t* hq   = prev + hoffq;
    const uint32_t* inq  = (L==0) ? (gXq + (size_t)t * IDIM) : (prev + ioffq);
    const int       ldq  = (L==0) ? (TT * IDIM) : NPin;
    uint32_t*       hout = gHq[wp] + hoffq;

    const int tid  = threadIdx.x;
    const int lane = tid & 31;
    const int warp = tid >> 5;
    const int g    = lane >> 2;
    const int tig  = lane & 3;
    const int rowBase = (bidx / COLT) * 64;
    const int colBase = (bidx % COLT) * 16;

    float acc[2][3][4];
#pragma unroll
    for (int nt = 0; nt < 2; nt++)
#pragma unroll
        for (int m = 0; m < 3; m++)
#pragma unroll
            for (int q = 0; q < 4; q++) acc[nt][m][q] = 0.f;

    // ---- cp.async tile issue: A 512 chunks, B 384 chunks (16B each) ----
    auto issue = [&](int kt, int st) {
#pragma unroll
        for (int i = 0; i < 4; i++) {
            int idx = tid + i * 128;
            int r = idx >> 3, ch = idx & 7;
            int g0 = kt * 32 + ch * 4;                 // word offset in A row
            const uint32_t* src = (g0 < n4)
                ? (hq  + (size_t)(rowBase + r) * n4  + g0)
                : (inq + (size_t)(rowBase + r) * ldq + (g0 - n4));
            cp16p(&As[st][r][ch * 4], src, g0 < AW);
        }
#pragma unroll
        for (int i = 0; i < 3; i++) {
            int idx = tid + i * 128;
            int mat = idx >> 7;
            int r = idx & 127;
            int c = r >> 3, ch = r & 7;
            int jn = colBase + c;
            const uint32_t* src =
                ((mat == 0) ? gWq1 : (mat == 1) ? gWq2 : gWqab)
                + qoff + (size_t)(jn < n ? jn : 0) * KW + kt * 32 + ch * 4;
            cp16p(&Bs[st][mat][c][ch * 4], src, jn < n);
        }
    };

    issue(0, 0);
    cp_commit();

    for (int kt = 0; kt < NT; kt++) {
        const int st = kt & 1;
        if (kt + 1 < NT) {
            issue(kt + 1, st ^ 1);
            cp_commit();
            cp_wait<1>();
        } else {
            cp_wait<0>();
        }
        __syncthreads();

        // ---- hoist ALL fragments for this k-tile (pure LDS.64, no CVTs) ----
        const int r0 = warp * 16 + g;
        uint32_t ahi[2][4], alo[2][4];
#pragma unroll
        for (int c16 = 0; c16 < 2; c16++) {
            const int wo = 2 * (c16 * 8 + tig);
            uint2 p0 = *(const uint2*)&As[st][r0][wo];
            uint2 p1 = *(const uint2*)&As[st][r0 + 8][wo];
            uint2 p2 = *(const uint2*)&As[st][r0][wo + 8];
            uint2 p3 = *(const uint2*)&As[st][r0 + 8][wo + 8];
            ahi[c16][0] = p0.x; ahi[c16][1] = p1.x; ahi[c16][2] = p2.x; ahi[c16][3] = p3.x;
            alo[c16][0] = p0.y; alo[c16][1] = p1.y; alo[c16][2] = p2.y; alo[c16][3] = p3.y;
        }
        uint2 bw0[2][2][3], bw1[2][2][3];   // [c16][nt][m]
#pragma unroll
        for (int c16 = 0; c16 < 2; c16++)
#pragma unroll
            for (int nt = 0; nt < 2; nt++)
#pragma unroll
                for (int m = 0; m < 3; m++) {
                    bw0[c16][nt][m] = *(const uint2*)&Bs[st][m][nt * 8 + g][2 * (c16 * 8 + tig)];
                    bw1[c16][nt][m] = *(const uint2*)&Bs[st][m][nt * 8 + g][2 * (c16 * 8 + tig + 4)];
                }

        // ---- MMA burst: 6 independent accumulator chains ----
#pragma unroll
        for (int nt = 0; nt < 2; nt++) {
#pragma unroll
            for (int m = 0; m < 3; m++) {
#pragma unroll
                for (int c16 = 0; c16 < 2; c16++) {
                    mma16816(acc[nt][m], ahi[c16], bw0[c16][nt][m].x, bw1[c16][nt][m].x);
                    mma16816(acc[nt][m], ahi[c16], bw0[c16][nt][m].y, bw1[c16][nt][m].y);
                    mma16816(acc[nt][m], alo[c16], bw0[c16][nt][m].x, bw1[c16][nt][m].x);
                }
            }
        }
        __syncthreads();
    }

    // ---- fused CfC epilogue: pack column pairs, store packed hi/lo ----
    const int r0g = rowBase + warp * 16 + g;
#pragma unroll
    for (int nt = 0; nt < 2; nt++) {
        const int j0 = colBase + nt * 8 + 2 * tig;   // even; n even -> pair in-range
        if (j0 < n) {
            const float vb1a = b1[j0], vb1b = b1[j0 + 1];
            const float vb2a = b2[j0], vb2b = b2[j0 + 1];
            const float vbsa = ba[j0] + bb[j0], vbsb = ba[j0 + 1] + bb[j0 + 1];
#pragma unroll
            for (int half = 0; half < 2; half++) {
                const int gr = r0g + half * 8;
                const float f1a = tanhf(acc[nt][0][half * 2 + 0] + vb1a);
                const float f1b = tanhf(acc[nt][0][half * 2 + 1] + vb1b);
                const float f2a = tanhf(acc[nt][1][half * 2 + 0] + vb2a);
                const float f2b = tanhf(acc[nt][1][half * 2 + 1] + vb2b);
                const float tia = 1.f / (1.f + expf(-(acc[nt][2][half * 2 + 0] + vbsa)));
                const float tib = 1.f / (1.f + expf(-(acc[nt][2][half * 2 + 1] + vbsb)));
                const float hva = f1a + tia * (f2a - f1a);
                const float hvb = f1b + tib * (f2b - f1b);
                uint32_t hi, lo;
                split2(hva, hvb, hi, lo);
                *(uint2*)&hout[(size_t)gr * n4 + j0] = make_uint2(hi, lo);
                if (L == 2) {
                    float* o = out + (size_t)gr * (TT * OUTD) + (size_t)t * OUTD + j0;
                    o[0] = hva;
                    o[1] = hvb;
                }
            }
        }
    }
}

// ---------------------------------------------------------------------------
// One wavefront: layer l active when 0 <= s-l < 128.
// ---------------------------------------------------------------------------
__global__ __launch_bounds__(128, 4) void wave_kernel(
    int s,
    const float* __restrict__ b1_0, const float* __restrict__ b2_0,
    const float* __restrict__ ba_0, const float* __restrict__ bb_0,
    const float* __restrict__ b1_1, const float* __restrict__ b2_1,
    const float* __restrict__ ba_1, const float* __restrict__ bb_1,
    const float* __restrict__ b1_2, const float* __restrict__ b2_2,
    const float* __restrict__ ba_2, const float* __restrict__ bb_2,
    float* __restrict__ out)
{
    __shared__ uint32_t As[2][64][AAP];
    __shared__ uint32_t Bs[2][3][16][WP];

    const int bx = blockIdx.x;
    const int wp = s & 1;

    if (bx < BLK_L0) {
        if (s < TT)
            cell_mma<0>(bx, s, wp, b1_0, b2_0, ba_0, bb_0, nullptr, As, Bs);
    } else if (bx < BLK_L0 + BLK_L1) {
        int t = s - 1;
        if (t >= 0 && t < TT)
            cell_mma<1>(bx - BLK_L0, t, wp, b1_1, b2_1, ba_1, bb_1, nullptr, As, Bs);
    } else {
        int t = s - 2;
        if (t >= 0 && t < TT)
            cell_mma<2>(bx - BLK_L0 - BLK_L1, t, wp, b1_2, b2_2, ba_2, bb_2, out, As, Bs);
    }
}

// ---------------------------------------------------------------------------
// Final FC, in-place on d_out predictions region.
// ---------------------------------------------------------------------------
__global__ __launch_bounds__(256) void fc_kernel(float* __restrict__ pred,
                                                 const float* __restrict__ Wfc,
                                                 const float* __restrict__ bfc)
{
    __shared__ float As[64][129];
    const int tid  = threadIdx.x;
    const int lane = tid & 31;
    const int wrp  = tid >> 5;
    float* base = pred + (size_t)blockIdx.x * 64 * OUTD;

    for (int e = tid; e < 64 * OUTD; e += 256)
        As[e >> 7][e & 127] = base[e];
    __syncthreads();

    for (int jj = 0; jj < 16; jj++) {
        int j = jj * 8 + wrp;
        float acc0 = bfc[j], acc1 = bfc[j];
        const float* wr = Wfc + j * OUTD;
#pragma unroll 8
        for (int k = 0; k < OUTD; k++) {
            float wv = wr[k];
            acc0 += As[lane][k] * wv;
            acc1 += As[lane + 32][k] * wv;
        }
        base[lane * OUTD + j]        = acc0;
        base[(lane + 32) * OUTD + j] = acc1;
    }
}

// ---------------------------------------------------------------------------
extern "C" void kernel_launch(void* const* d_in, const int* in_sizes, int n_in,
                              void* d_out, int out_size)
{
    const float* x    = (const float*)d_in[0];
    const float* h0   = (const float*)d_in[1];

    const float* mask0 = (const float*)d_in[2];
    const float* W1_0  = (const float*)d_in[3];
    const float* W2_0  = (const float*)d_in[4];
    const float* Wa_0  = (const float*)d_in[5];
    const float* Wb_0  = (const float*)d_in[6];
    const float* b1_0  = (const float*)d_in[7];
    const float* b2_0  = (const float*)d_in[8];
    const float* ba_0  = (const float*)d_in[9];
    const float* bb_0  = (const float*)d_in[10];

    const float* mask1 = (const float*)d_in[11];
    const float* W1_1  = (const float*)d_in[12];
    const float* W2_1  = (const float*)d_in[13];
    const float* Wa_1  = (const float*)d_in[14];
    const float* Wb_1  = (const float*)d_in[15];
    const float* b1_1  = (const float*)d_in[16];
    const float* b2_1  = (const float*)d_in[17];
    const float* ba_1  = (const float*)d_in[18];
    const float* bb_1  = (const float*)d_in[19];

    const float* mask2 = (const float*)d_in[20];
    const float* W1_2  = (const float*)d_in[21];
    const float* W2_2  = (const float*)d_in[22];
    const float* Wa_2  = (const float*)d_in[23];
    const float* Wb_2  = (const float*)d_in[24];
    const float* b1_2  = (const float*)d_in[25];
    const float* b2_2  = (const float*)d_in[26];
    const float* ba_2  = (const float*)d_in[27];
    const float* bb_2  = (const float*)d_in[28];

    const float* Wfc  = (const float*)d_in[29];
    const float* bfc  = (const float*)d_in[30];

    float* out = (float*)d_out;

    prep_kernel<<<2048, 256>>>(W1_0, W2_0, Wa_0, Wb_0, mask0,
                               W1_1, W2_1, Wa_1, Wb_1, mask1,
                               W1_2, W2_2, Wa_2, Wb_2, mask2);
    prep_x_kernel<<<2048, 256>>>(x);
    init_h_kernel<<<512, 256>>>(h0);

    // Wavefront sweep: s = 0 .. 129 (layer l computes t = s - l)
    for (int s = 0; s < TT + 2; s++) {
        wave_kernel<<<BLK_TOT, 128>>>(s,
                                      b1_0, b2_0, ba_0, bb_0,
                                      b1_1, b2_1, ba_1, bb_1,
                                      b1_2, b2_2, ba_2, bb_2,
                                      out);
    }

    // predictions = motor @ Wfc^T + bfc (in place)
    fc_kernel<<<(BB * TT) / 64, 256>>>(out, Wfc, bfc);

    if (out_size >= BB * TT * OUTD + BB * 1024)
        copy_hn_kernel<<<512, 256>>>(out + (size_t)BB * TT * OUTD);
}

// round 17
// speedup vs baseline: 1.5010x; 1.3916x over previous
#include <cuda_runtime.h>
#include <cuda_fp16.h>
#include <math.h>
#include <stdint.h>

// ---------------------------------------------------------------------------
// CfC / AutoNCP decoder — wavefront-pipelined, mma.sync fp16, 2-pass split:
//   D = Ahi*B + Alo*B      (A split to fp16 hi/lo ~22-bit; B single fp16)
// 24 HMMA per warp per k-tile (was 36) — attacks the saturated legacy HMMA
// pipe identified as the binding resource.
// A (h and x) stored packed: word 2p = fp16x2{hi(2p),hi(2p+1)}, 2p+1 = lo pair.
// B stored single-plane fp16, k-pairs interleaved (p, p+4) so one LDS.64
// fetches both mma B registers.
//   layer l at wavefront s computes t = s - l
// ---------------------------------------------------------------------------

#define BB   512
#define TT   128
#define IDIM 512
#define OUTD 128

#define N0 538
#define N1 358
#define N2 128

// padded h widths (row strides in words == elements)
#define NP0 544
#define NP1 360
#define NP2P 128
// input-region padded widths
#define NPIN0 512
#define NPIN1 NP0
#define NPIN2 NP1
// total A-row words per layer and k-tiles of 32 elements
#define AW0 (NP0 + NPIN0)   // 1056
#define AW1 (NP1 + NPIN1)   // 904
#define AW2 (NP2P + NPIN2)  // 488
#define NT0 33
#define NT1 29
#define NT2 16
// single-plane fp16 weight row strides: 16 words per 32-elem k-tile
#define KWH0 (NT0*16)   // 528
#define KWH1 (NT1*16)   // 464
#define KWH2 (NT2*16)   // 256

#define QH0 (N0*KWH0)
#define QH1 (N1*KWH1)
#define QH2 (N2*KWH2)
#define QHOFF1 (QH0)
#define QHOFF2 (QH0+QH1)
#define QHTOT  (QH0+QH1+QH2)

// packed hidden-state offsets (words)
#define OFFQ0 0
#define OFFQ1 (BB*NP0)
#define OFFQ2 (BB*(NP0+NP1))
#define HTOTQ (BB*(NP0+NP1+NP2P))

// wavefront grid partition (BM=64, BN=16)
#define BLK_L0 272    // 34 col-tiles x 8 row-tiles
#define BLK_L1 184    // 23 x 8
#define BLK_L2 64     //  8 x 8
#define BLK_TOT (BLK_L0 + BLK_L1 + BLK_L2)   // 520

// Static device scratch (zero-initialized at module load; pads never written)
__device__ __align__(16) uint32_t gWq1[QHTOT];
__device__ __align__(16) uint32_t gWq2[QHTOT];
__device__ __align__(16) uint32_t gWqab[QHTOT];
__device__ __align__(16) uint32_t gHq[2][HTOTQ];
__device__ __align__(16) uint32_t gXq[BB * TT * IDIM];

// ---------------------------------------------------------------------------
// helpers (fp16)
// ---------------------------------------------------------------------------
__device__ __forceinline__ void split2h(float f0, float f1, uint32_t& hi, uint32_t& lo)
{
    __half h0 = __float2half_rn(f0);
    __half h1 = __float2half_rn(f1);
    float r0 = f0 - __half2float(h0);
    float r1 = f1 - __half2float(h1);
    __half l0 = __float2half_rn(r0);
    __half l1 = __float2half_rn(r1);
    hi = ((uint32_t)__half_as_ushort(h1) << 16) | (uint32_t)__half_as_ushort(h0);
    lo = ((uint32_t)__half_as_ushort(l1) << 16) | (uint32_t)__half_as_ushort(l0);
}
__device__ __forceinline__ uint32_t packh2(float f0, float f1)
{
    __half h0 = __float2half_rn(f0);
    __half h1 = __float2half_rn(f1);
    return ((uint32_t)__half_as_ushort(h1) << 16) | (uint32_t)__half_as_ushort(h0);
}
__device__ __forceinline__ float hf_lo(uint32_t w)
{
    return __half2float(__ushort_as_half((unsigned short)(w & 0xffff)));
}
__device__ __forceinline__ float hf_hi(uint32_t w)
{
    return __half2float(__ushort_as_half((unsigned short)(w >> 16)));
}

__device__ __forceinline__ void mma16816h(float* c, const uint32_t* a, uint32_t b0, uint32_t b1)
{
    asm volatile(
        "mma.sync.aligned.m16n8k16.row.col.f32.f16.f16.f32 "
        "{%0,%1,%2,%3}, {%4,%5,%6,%7}, {%8,%9}, {%0,%1,%2,%3};\n"
        : "+f"(c[0]), "+f"(c[1]), "+f"(c[2]), "+f"(c[3])
        : "r"(a[0]), "r"(a[1]), "r"(a[2]), "r"(a[3]), "r"(b0), "r"(b1));
}

__device__ __forceinline__ void cp16p(void* dst, const void* src, bool pred)
{
    uint32_t d = (uint32_t)__cvta_generic_to_shared(dst);
    const void* s = pred ? src : (const void*)gWq1;   // 16B-aligned safe address
    int sz = pred ? 16 : 0;                            // 0 -> zero-fill 16B
    asm volatile("cp.async.cg.shared.global [%0], [%1], 16, %2;\n"
                 :: "r"(d), "l"(s), "r"(sz) : "memory");
}
__device__ __forceinline__ void cp_commit() { asm volatile("cp.async.commit_group;\n" ::: "memory"); }
template <int N>
__device__ __forceinline__ void cp_wait() { asm volatile("cp.async.wait_group %0;\n" :: "n"(N) : "memory"); }

// ---------------------------------------------------------------------------
// prep: single-plane fp16 weights, k' order = [own h (n4), input (NPin)],
// k-pairs interleaved within each 8-pair half-tile: word order
// [p, p+4] adjacent so one LDS.64 fetches both mma B registers.
//   word w in row: kt = w>>4, r = w&15, c16 = r>>3, tig = (r&7)>>1, half = r&1
//   pair = kt*16 + c16*8 + tig + 4*half
// ---------------------------------------------------------------------------
__device__ __forceinline__ int remap_k(int kp, int n, int n4, int in_real)
{
    if (kp < n4) return (kp < n) ? (in_real + kp) : -1;
    int ks = kp - n4;
    return (ks < in_real) ? ks : -1;
}

__global__ void prep_kernel(
    const float* __restrict__ W1_0, const float* __restrict__ W2_0,
    const float* __restrict__ Wa_0, const float* __restrict__ Wb_0, const float* __restrict__ m0,
    const float* __restrict__ W1_1, const float* __restrict__ W2_1,
    const float* __restrict__ Wa_1, const float* __restrict__ Wb_1, const float* __restrict__ m1,
    const float* __restrict__ W1_2, const float* __restrict__ W2_2,
    const float* __restrict__ Wa_2, const float* __restrict__ Wb_2, const float* __restrict__ m2)
{
    for (int i = blockIdx.x * blockDim.x + threadIdx.x; i < QHTOT; i += gridDim.x * blockDim.x) {
        const float *W1, *W2, *Wa, *Wb, *m;
        int li, n, n4, in_real, K, KWH;
        if (i < QHOFF1) {
            W1=W1_0; W2=W2_0; Wa=Wa_0; Wb=Wb_0; m=m0;
            li=i; n=N0; n4=NP0; in_real=IDIM; KWH=KWH0;
        } else if (i < QHOFF2) {
            W1=W1_1; W2=W2_1; Wa=Wa_1; Wb=Wb_1; m=m1;
            li=i-QHOFF1; n=N1; n4=NP1; in_real=N0; KWH=KWH1;
        } else {
            W1=W1_2; W2=W2_2; Wa=Wa_2; Wb=Wb_2; m=m2;
            li=i-QHOFF2; n=N2; n4=NP2P; in_real=N1; KWH=KWH2;
        }
        K = in_real + n;
        int j  = li / KWH;
        int w  = li - j * KWH;
        int kt = w >> 4;
        int r  = w & 15;
        int c16 = r >> 3, tig = (r & 7) >> 1, half = r & 1;
        int pair = kt * 16 + c16 * 8 + tig + 4 * half;
        int s0 = remap_k(2 * pair,     n, n4, in_real);
        int s1 = remap_k(2 * pair + 1, n, n4, in_real);

        float a0=0.f, a1=0.f, b0v=0.f, b1v=0.f, c0=0.f, c1=0.f;
        if (s0 >= 0) {
            int ix = j*K + s0; float mm = m[ix];
            a0 = W1[ix]*mm; b0v = W2[ix]*mm; c0 = Wa[ix] + Wb[ix];
        }
        if (s1 >= 0) {
            int ix = j*K + s1; float mm = m[ix];
            a1 = W1[ix]*mm; b1v = W2[ix]*mm; c1 = Wa[ix] + Wb[ix];
        }
        gWq1[i]  = packh2(a0,  a1);
        gWq2[i]  = packh2(b0v, b1v);
        gWqab[i] = packh2(c0,  c1);
    }
}

// pre-split x into packed fp16 hi/lo words
__global__ void prep_x_kernel(const float* __restrict__ x)
{
    const int total = BB * TT * IDIM / 2;
    for (int p = blockIdx.x * blockDim.x + threadIdx.x; p < total; p += gridDim.x * blockDim.x) {
        float2 v = *(const float2*)(x + 2 * (size_t)p);
        uint32_t hi, lo;
        split2h(v.x, v.y, hi, lo);
        gXq[2 * (size_t)p]     = hi;
        gXq[2 * (size_t)p + 1] = lo;
    }
}

// h0 -> packed per-layer state, both parities
__global__ void init_h_kernel(const float* __restrict__ h0)
{
    const int total = BB * 512;
    for (int idx = blockIdx.x * blockDim.x + threadIdx.x; idx < total; idx += gridDim.x * blockDim.x) {
        int b = idx >> 9;
        int p = idx & 511;
        int c0 = 2 * p;
        int off, lc0;
        if (c0 < N0)           { off = OFFQ0 + b * NP0;  lc0 = c0; }
        else if (c0 < N0 + N1) { off = OFFQ1 + b * NP1;  lc0 = c0 - N0; }
        else                   { off = OFFQ2 + b * NP2P; lc0 = c0 - N0 - N1; }
        uint32_t hi, lo;
        split2h(h0[b * 1024 + c0], h0[b * 1024 + c0 + 1], hi, lo);
        gHq[0][off + lc0]     = hi;
        gHq[0][off + lc0 + 1] = lo;
        gHq[1][off + lc0]     = hi;
        gHq[1][off + lc0 + 1] = lo;
    }
}

// final h: layer0 parity 1 (s=127), layer1 parity 0 (s=128), layer2 parity 1 (s=129)
__global__ void copy_hn_kernel(float* __restrict__ hn)
{
    const int total = BB * 512;
    for (int idx = blockIdx.x * blockDim.x + threadIdx.x; idx < total; idx += gridDim.x * blockDim.x) {
        int b = idx >> 9;
        int p = idx & 511;
        int c0 = 2 * p;
        const uint32_t* src;
        int lc0;
        if (c0 < N0)           { src = gHq[1] + OFFQ0 + b * NP0;  lc0 = c0; }
        else if (c0 < N0 + N1) { src = gHq[0] + OFFQ1 + b * NP1;  lc0 = c0 - N0; }
        else                   { src = gHq[1] + OFFQ2 + b * NP2P; lc0 = c0 - N0 - N1; }
        uint32_t hi = src[lc0], lo = src[lc0 + 1];
        hn[b * 1024 + c0]     = hf_lo(hi) + hf_lo(lo);
        hn[b * 1024 + c0 + 1] = hf_hi(hi) + hf_hi(lo);
    }
}

// smem strides (words): conflict-free LDS.64 phases verified:
//   A (AAP=40): bank = (8g + 2tig) mod 32, distinct per phase
//   B (WP=24):  bank = (24g + 2tig) mod 32 -> {0..6,24..30,16..22,8..14} distinct
#define AAP 40   // As[row][word], 32 words used per k-tile
#define WP  24   // Bs[mat][col][word], 16 words used per k-tile

// ---------------------------------------------------------------------------
// Fused CfC cell, mma.sync fp16 2-pass. 128 threads = 4 warps.
//   BM=64 (warp w: rows w*16..w*16+15), BN=16 (2 n8 tiles), BK=32 elements.
//   Per k-tile per warp: 8 A LDS.64 + 12 B LDS.64 + 24 HMMA.
// ---------------------------------------------------------------------------
template <int L>
__device__ __forceinline__ void cell_mma(
    int bidx, int t, int wp,
    const float* __restrict__ b1, const float* __restrict__ b2,
    const float* __restrict__ ba, const float* __restrict__ bb,
    float* __restrict__ out,
    uint32_t (*As)[64][AAP], uint32_t (*Bs)[3][16][WP])
{
    constexpr int n    = (L==0) ? N0 : (L==1) ? N1 : N2;
    constexpr int n4   = (L==0) ? NP0 : (L==1) ? NP1 : NP2P;
    constexpr int NPin = (L==0) ? NPIN0 : (L==1) ? NPIN1 : NPIN2;
    constexpr int AW   = n4 + NPin;
    constexpr int NT   = (L==0) ? NT0 : (L==1) ? NT1 : NT2;
    constexpr int KWH  = NT * 16;
    constexpr int COLT = (L==0) ? 34 : (L==1) ? 23 : 8;
    constexpr int hoffq = (L==0) ? OFFQ0 : (L==1) ? OFFQ1 : OFFQ2;
    constexpr int qoff  = (L==0) ? 0 : (L==1) ? QHOFF1 : QHOFF2;
    constexpr int ioffq = (L==1) ? OFFQ0 : (L==2) ? OFFQ1 : 0;

    const uint32_t* prev = gHq[wp ^ 1];
    const uint32_t* hq   = prev + hoffq;
    const uint32_t* inq  = (L==0) ? (gXq + (size_t)t * IDIM) : (prev + ioffq);
    const int       ldq  = (L==0) ? (TT * IDIM) : NPin;
    uint32_t*       hout = gHq[wp] + hoffq;

    const int tid  = threadIdx.x;
    const int lane = tid & 31;
    const int warp = tid >> 5;
    const int g    = lane >> 2;
    const int tig  = lane & 3;
    const int rowBase = (bidx / COLT) * 64;
    const int colBase = (bidx % COLT) * 16;

    float acc[2][3][4];
#pragma unroll
    for (int nt = 0; nt < 2; nt++)
#pragma unroll
        for (int m = 0; m < 3; m++)
#pragma unroll
            for (int q = 0; q < 4; q++) acc[nt][m][q] = 0.f;

    // ---- cp.async tile issue: A 512 chunks, B 192 chunks (16B each) ----
    auto issue = [&](int kt, int st) {
#pragma unroll
        for (int i = 0; i < 4; i++) {
            int idx = tid + i * 128;
            int r = idx >> 3, ch = idx & 7;
            int g0 = kt * 32 + ch * 4;                 // word offset in A row
            const uint32_t* src = (g0 < n4)
                ? (hq  + (size_t)(rowBase + r) * n4  + g0)
                : (inq + (size_t)(rowBase + r) * ldq + (g0 - n4));
            cp16p(&As[st][r][ch * 4], src, g0 < AW);
        }
#pragma unroll
        for (int i = 0; i < 2; i++) {
            int idx = tid + i * 128;
            if (idx < 192) {
                int mat = idx >> 6;            // 0..2
                int r = idx & 63;
                int c = r >> 2, ch = r & 3;    // c 0..15, ch 0..3
                int jn = colBase + c;
                const uint32_t* src =
                    ((mat == 0) ? gWq1 : (mat == 1) ? gWq2 : gWqab)
                    + qoff + (size_t)(jn < n ? jn : 0) * KWH + kt * 16 + ch * 4;
                cp16p(&Bs[st][mat][c][ch * 4], src, jn < n);
            }
        }
    };

    issue(0, 0);
    cp_commit();

    for (int kt = 0; kt < NT; kt++) {
        const int st = kt & 1;
        if (kt + 1 < NT) {
            issue(kt + 1, st ^ 1);
            cp_commit();
            cp_wait<1>();
        } else {
            cp_wait<0>();
        }
        __syncthreads();

        // ---- hoist ALL fragments for this k-tile (pure LDS.64, no CVTs) ----
        const int r0 = warp * 16 + g;
        uint32_t ahi[2][4], alo[2][4];
#pragma unroll
        for (int c16 = 0; c16 < 2; c16++) {
            const int wo = 2 * (c16 * 8 + tig);
            uint2 p0 = *(const uint2*)&As[st][r0][wo];
            uint2 p1 = *(const uint2*)&As[st][r0 + 8][wo];
            uint2 p2 = *(const uint2*)&As[st][r0][wo + 8];
            uint2 p3 = *(const uint2*)&As[st][r0 + 8][wo + 8];
            ahi[c16][0] = p0.x; ahi[c16][1] = p1.x; ahi[c16][2] = p2.x; ahi[c16][3] = p3.x;
            alo[c16][0] = p0.y; alo[c16][1] = p1.y; alo[c16][2] = p2.y; alo[c16][3] = p3.y;
        }
        // B: one LDS.64 per (c16, nt, m) fetches both b-regs (pairs p and p+4)
        uint2 bw[2][2][3];
#pragma unroll
        for (int c16 = 0; c16 < 2; c16++)
#pragma unroll
            for (int nt = 0; nt < 2; nt++)
#pragma unroll
                for (int m = 0; m < 3; m++)
                    bw[c16][nt][m] = *(const uint2*)&Bs[st][m][nt * 8 + g][c16 * 8 + 2 * tig];

        // ---- MMA burst: 24 HMMA on 6 independent accumulator chains ----
#pragma unroll
        for (int nt = 0; nt < 2; nt++) {
#pragma unroll
            for (int m = 0; m < 3; m++) {
#pragma unroll
                for (int c16 = 0; c16 < 2; c16++) {
                    mma16816h(acc[nt][m], ahi[c16], bw[c16][nt][m].x, bw[c16][nt][m].y);
                    mma16816h(acc[nt][m], alo[c16], bw[c16][nt][m].x, bw[c16][nt][m].y);
                }
            }
        }
        __syncthreads();
    }

    // ---- fused CfC epilogue: pack column pairs, store packed hi/lo ----
    const int r0g = rowBase + warp * 16 + g;
#pragma unroll
    for (int nt = 0; nt < 2; nt++) {
        const int j0 = colBase + nt * 8 + 2 * tig;   // even; n even -> pair in-range
        if (j0 < n) {
            const float vb1a = b1[j0], vb1b = b1[j0 + 1];
            const float vb2a = b2[j0], vb2b = b2[j0 + 1];
            const float vbsa = ba[j0] + bb[j0], vbsb = ba[j0 + 1] + bb[j0 + 1];
#pragma unroll
            for (int half = 0; half < 2; half++) {
                const int gr = r0g + half * 8;
                const float f1a = tanhf(acc[nt][0][half * 2 + 0] + vb1a);
                const float f1b = tanhf(acc[nt][0][half * 2 + 1] + vb1b);
                const float f2a = tanhf(acc[nt][1][half * 2 + 0] + vb2a);
                const float f2b = tanhf(acc[nt][1][half * 2 + 1] + vb2b);
                const float tia = 1.f / (1.f + expf(-(acc[nt][2][half * 2 + 0] + vbsa)));
                const float tib = 1.f / (1.f + expf(-(acc[nt][2][half * 2 + 1] + vbsb)));
                const float hva = f1a + tia * (f2a - f1a);
                const float hvb = f1b + tib * (f2b - f1b);
                uint32_t hi, lo;
                split2h(hva, hvb, hi, lo);
                *(uint2*)&hout[(size_t)gr * n4 + j0] = make_uint2(hi, lo);
                if (L == 2) {
                    float* o = out + (size_t)gr * (TT * OUTD) + (size_t)t * OUTD + j0;
                    o[0] = hva;
                    o[1] = hvb;
                }
            }
        }
    }
}

// ---------------------------------------------------------------------------
// One wavefront: layer l active when 0 <= s-l < 128.
// ---------------------------------------------------------------------------
__global__ __launch_bounds__(128, 4) void wave_kernel(
    int s,
    const float* __restrict__ b1_0, const float* __restrict__ b2_0,
    const float* __restrict__ ba_0, const float* __restrict__ bb_0,
    const float* __restrict__ b1_1, const float* __restrict__ b2_1,
    const float* __restrict__ ba_1, const float* __restrict__ bb_1,
    const float* __restrict__ b1_2, const float* __restrict__ b2_2,
    const float* __restrict__ ba_2, const float* __restrict__ bb_2,
    float* __restrict__ out)
{
    __shared__ uint32_t As[2][64][AAP];
    __shared__ uint32_t Bs[2][3][16][WP];

    const int bx = blockIdx.x;
    const int wp = s & 1;

    if (bx < BLK_L0) {
        if (s < TT)
            cell_mma<0>(bx, s, wp, b1_0, b2_0, ba_0, bb_0, nullptr, As, Bs);
    } else if (bx < BLK_L0 + BLK_L1) {
        int t = s - 1;
        if (t >= 0 && t < TT)
            cell_mma<1>(bx - BLK_L0, t, wp, b1_1, b2_1, ba_1, bb_1, nullptr, As, Bs);
    } else {
        int t = s - 2;
        if (t >= 0 && t < TT)
            cell_mma<2>(bx - BLK_L0 - BLK_L1, t, wp, b1_2, b2_2, ba_2, bb_2, out, As, Bs);
    }
}

// ---------------------------------------------------------------------------
// Final FC, in-place on d_out predictions region.
// ---------------------------------------------------------------------------
__global__ __launch_bounds__(256) void fc_kernel(float* __restrict__ pred,
                                                 const float* __restrict__ Wfc,
                                                 const float* __restrict__ bfc)
{
    __shared__ float As[64][129];
    const int tid  = threadIdx.x;
    const int lane = tid & 31;
    const int wrp  = tid >> 5;
    float* base = pred + (size_t)blockIdx.x * 64 * OUTD;

    for (int e = tid; e < 64 * OUTD; e += 256)
        As[e >> 7][e & 127] = base[e];
    __syncthreads();

    for (int jj = 0; jj < 16; jj++) {
        int j = jj * 8 + wrp;
        float acc0 = bfc[j], acc1 = bfc[j];
        const float* wr = Wfc + j * OUTD;
#pragma unroll 8
        for (int k = 0; k < OUTD; k++) {
            float wv = wr[k];
            acc0 += As[lane][k] * wv;
            acc1 += As[lane + 32][k] * wv;
        }
        base[lane * OUTD + j]        = acc0;
        base[(lane + 32) * OUTD + j] = acc1;
    }
}

// ---------------------------------------------------------------------------
extern "C" void kernel_launch(void* const* d_in, const int* in_sizes, int n_in,
                              void* d_out, int out_size)
{
    const float* x    = (const float*)d_in[0];
    const float* h0   = (const float*)d_in[1];

    const float* mask0 = (const float*)d_in[2];
    const float* W1_0  = (const float*)d_in[3];
    const float* W2_0  = (const float*)d_in[4];
    const float* Wa_0  = (const float*)d_in[5];
    const float* Wb_0  = (const float*)d_in[6];
    const float* b1_0  = (const float*)d_in[7];
    const float* b2_0  = (const float*)d_in[8];
    const float* ba_0  = (const float*)d_in[9];
    const float* bb_0  = (const float*)d_in[10];

    const float* mask1 = (const float*)d_in[11];
    const float* W1_1  = (const float*)d_in[12];
    const float* W2_1  = (const float*)d_in[13];
    const float* Wa_1  = (const float*)d_in[14];
    const float* Wb_1  = (const float*)d_in[15];
    const float* b1_1  = (const float*)d_in[16];
    const float* b2_1  = (const float*)d_in[17];
    const float* ba_1  = (const float*)d_in[18];
    const float* bb_1  = (const float*)d_in[19];

    const float* mask2 = (const float*)d_in[20];
    const float* W1_2  = (const float*)d_in[21];
    const float* W2_2  = (const float*)d_in[22];
    const float* Wa_2  = (const float*)d_in[23];
    const float* Wb_2  = (const float*)d_in[24];
    const float* b1_2  = (const float*)d_in[25];
    const float* b2_2  = (const float*)d_in[26];
    const float* ba_2  = (const float*)d_in[27];
    const float* bb_2  = (const float*)d_in[28];

    const float* Wfc  = (const float*)d_in[29];
    const float* bfc  = (const float*)d_in[30];

    float* out = (float*)d_out;

    prep_kernel<<<2048, 256>>>(W1_0, W2_0, Wa_0, Wb_0, mask0,
                               W1_1, W2_1, Wa_1, Wb_1, mask1,
                               W1_2, W2_2, Wa_2, Wb_2, mask2);
    prep_x_kernel<<<2048, 256>>>(x);
    init_h_kernel<<<512, 256>>>(h0);

    // Wavefront sweep: s = 0 .. 129 (layer l computes t = s - l)
    for (int s = 0; s < TT + 2; s++) {
        wave_kernel<<<BLK_TOT, 128>>>(s,
                                      b1_0, b2_0, ba_0, bb_0,
                                      b1_1, b2_1, ba_1, bb_1,
                                      b1_2, b2_2, ba_2, bb_2,
                                      out);
    }

    // predictions = motor @ Wfc^T + bfc (in place)
    fc_kernel<<<(BB * TT) / 64, 256>>>(out, Wfc, bfc);

    if (out_size >= BB * TT * OUTD + BB * 1024)
        copy_hn_kernel<<<512, 256>>>(out + (size_t)BB * TT * OUTD);
}